// round 1
// baseline (speedup 1.0000x reference)
#include <cuda_runtime.h>
#include <cstdint>
#include <math.h>

#define Bc   2
#define Sc   2048
#define TOK  4096
#define Ec   1024
#define Hc   16
#define HDc  64
#define MLPc 4096

// ---------------- scratch (no allocations allowed) ----------------
__device__ float g_z0[(size_t)TOK * Ec];
__device__ float g_q [(size_t)TOK * Ec];
__device__ float g_k [(size_t)TOK * Ec];
__device__ float g_v [(size_t)TOK * Ec];
__device__ float g_ctx[(size_t)TOK * Ec];
__device__ float g_x1[(size_t)TOK * Ec];
__device__ float g_z1[(size_t)TOK * Ec];
__device__ float g_h [(size_t)TOK * MLPc];

// ---------------- helpers ----------------
__device__ __forceinline__ unsigned f2tf(float f) {
    unsigned r;
    asm("cvt.rna.tf32.f32 %0, %1;" : "=r"(r) : "f"(f));
    return r;
}

__device__ __forceinline__ void mma8(float c[4], const unsigned a[4], const unsigned b[2]) {
    asm volatile(
        "mma.sync.aligned.m16n8k8.row.col.f32.tf32.tf32.f32 "
        "{%0,%1,%2,%3}, {%4,%5,%6,%7}, {%8,%9}, {%0,%1,%2,%3};\n"
        : "+f"(c[0]), "+f"(c[1]), "+f"(c[2]), "+f"(c[3])
        : "r"(a[0]), "r"(a[1]), "r"(a[2]), "r"(a[3]),
          "r"(b[0]), "r"(b[1]));
}

// ---------------- LayerNorm (fp32 exact) ----------------
__global__ void __launch_bounds__(256) ln_kernel(
    const float* __restrict__ x, const float* __restrict__ gam,
    const float* __restrict__ bet, float* __restrict__ y)
{
    const int row = blockIdx.x, t = threadIdx.x;
    const float4* xr = reinterpret_cast<const float4*>(x + (size_t)row * Ec);
    float4 v = xr[t];
    float s  = v.x + v.y + v.z + v.w;
    float ss = v.x*v.x + v.y*v.y + v.z*v.z + v.w*v.w;
    #pragma unroll
    for (int o = 16; o; o >>= 1) {
        s  += __shfl_xor_sync(0xffffffffu, s,  o);
        ss += __shfl_xor_sync(0xffffffffu, ss, o);
    }
    __shared__ float rs[8], rss[8];
    if ((t & 31) == 0) { rs[t >> 5] = s; rss[t >> 5] = ss; }
    __syncthreads();
    if (t < 32) {
        float a = (t < 8) ? rs[t]  : 0.f;
        float b = (t < 8) ? rss[t] : 0.f;
        #pragma unroll
        for (int o = 4; o; o >>= 1) {
            a += __shfl_xor_sync(0xffffffffu, a, o);
            b += __shfl_xor_sync(0xffffffffu, b, o);
        }
        if (t == 0) { rs[0] = a; rss[0] = b; }
    }
    __syncthreads();
    const float mu   = rs[0]  * (1.f / Ec);
    const float var  = rss[0] * (1.f / Ec) - mu * mu;
    const float rstd = rsqrtf(var + 1e-5f);
    float4 gv = reinterpret_cast<const float4*>(gam)[t];
    float4 bv = reinterpret_cast<const float4*>(bet)[t];
    float4 o;
    o.x = (v.x - mu) * rstd * gv.x + bv.x;
    o.y = (v.y - mu) * rstd * gv.y + bv.y;
    o.z = (v.z - mu) * rstd * gv.z + bv.z;
    o.w = (v.w - mu) * rstd * gv.w + bv.w;
    reinterpret_cast<float4*>(y + (size_t)row * Ec)[t] = o;
}

// ---------------- TF32 GEMM: C = A[M,K] @ W[K,N] + bias (+res / gelu) ----------------
// EPI: 0 = bias, 1 = bias + residual, 2 = bias + exact gelu
template <int EPI>
__global__ void __launch_bounds__(256, 2) gemm_kernel(
    const float* __restrict__ A, const float* __restrict__ W,
    const float* __restrict__ bias, const float* __restrict__ res,
    float* __restrict__ C, int M, int N, int K)
{
    __shared__ __align__(16) unsigned As[2][16][132];
    __shared__ __align__(16) unsigned Bs[2][16][132];
    const int t    = threadIdx.x;
    const int lane = t & 31, warp = t >> 5;
    const int wm = warp >> 1, wn = warp & 1;      // 4 x 2 warp grid
    const int g  = lane >> 2, t4 = lane & 3;
    const int bm = blockIdx.y * 128, bn = blockIdx.x * 128;

    float acc[2][8][4];
    #pragma unroll
    for (int mi = 0; mi < 2; mi++)
        #pragma unroll
        for (int ni = 0; ni < 8; ni++)
            #pragma unroll
            for (int c = 0; c < 4; c++) acc[mi][ni][c] = 0.f;

    const int am0 = t >> 2;            // A tile row (+ it*64)
    const int ak0 = (t & 3) * 4;       // A tile k (float4)
    const int bk0 = t >> 5;            // B tile k (+ it*8)
    const int bn0 = (t & 31) * 4;      // B tile n (float4)

    float4 ra[2], rb[2];
    // prologue: tile 0
    #pragma unroll
    for (int it = 0; it < 2; it++) {
        ra[it] = *reinterpret_cast<const float4*>(A + (size_t)(bm + am0 + it*64) * K + ak0);
        rb[it] = *reinterpret_cast<const float4*>(W + (size_t)(bk0 + it*8) * N + bn + bn0);
    }
    #pragma unroll
    for (int it = 0; it < 2; it++) {
        int am = am0 + it*64;
        As[0][ak0+0][am] = f2tf(ra[it].x); As[0][ak0+1][am] = f2tf(ra[it].y);
        As[0][ak0+2][am] = f2tf(ra[it].z); As[0][ak0+3][am] = f2tf(ra[it].w);
        uint4 u; u.x = f2tf(rb[it].x); u.y = f2tf(rb[it].y);
        u.z = f2tf(rb[it].z); u.w = f2tf(rb[it].w);
        *reinterpret_cast<uint4*>(&Bs[0][bk0 + it*8][bn0]) = u;
    }

    const int nt = K >> 4;
    int cur = 0;
    for (int tile = 0; tile < nt; tile++) {
        __syncthreads();
        const bool pre = (tile + 1 < nt);
        if (pre) {
            const int k0 = (tile + 1) << 4;
            #pragma unroll
            for (int it = 0; it < 2; it++) {
                ra[it] = *reinterpret_cast<const float4*>(A + (size_t)(bm + am0 + it*64) * K + k0 + ak0);
                rb[it] = *reinterpret_cast<const float4*>(W + (size_t)(k0 + bk0 + it*8) * N + bn + bn0);
            }
        }
        #pragma unroll
        for (int kk = 0; kk < 2; kk++) {
            const int kb = kk * 8;
            unsigned a[2][4];
            #pragma unroll
            for (int mi = 0; mi < 2; mi++) {
                int mr = wm*32 + mi*16 + g;
                a[mi][0] = As[cur][kb + t4    ][mr];
                a[mi][1] = As[cur][kb + t4    ][mr + 8];
                a[mi][2] = As[cur][kb + t4 + 4][mr];
                a[mi][3] = As[cur][kb + t4 + 4][mr + 8];
            }
            #pragma unroll
            for (int ni = 0; ni < 8; ni++) {
                unsigned bfr[2];
                int nc = wn*64 + ni*8 + g;
                bfr[0] = Bs[cur][kb + t4    ][nc];
                bfr[1] = Bs[cur][kb + t4 + 4][nc];
                mma8(acc[0][ni], a[0], bfr);
                mma8(acc[1][ni], a[1], bfr);
            }
        }
        if (pre) {
            const int nxt = cur ^ 1;
            #pragma unroll
            for (int it = 0; it < 2; it++) {
                int am = am0 + it*64;
                As[nxt][ak0+0][am] = f2tf(ra[it].x); As[nxt][ak0+1][am] = f2tf(ra[it].y);
                As[nxt][ak0+2][am] = f2tf(ra[it].z); As[nxt][ak0+3][am] = f2tf(ra[it].w);
                uint4 u; u.x = f2tf(rb[it].x); u.y = f2tf(rb[it].y);
                u.z = f2tf(rb[it].z); u.w = f2tf(rb[it].w);
                *reinterpret_cast<uint4*>(&Bs[nxt][bk0 + it*8][bn0]) = u;
            }
        }
        cur ^= 1;
    }

    // epilogue
    #pragma unroll
    for (int mi = 0; mi < 2; mi++) {
        #pragma unroll
        for (int half = 0; half < 2; half++) {
            const int row = bm + wm*32 + mi*16 + g + half*8;
            #pragma unroll
            for (int ni = 0; ni < 8; ni++) {
                const int col = bn + wn*64 + ni*8 + t4*2;
                float vx = acc[mi][ni][half*2 + 0] + __ldg(bias + col);
                float vy = acc[mi][ni][half*2 + 1] + __ldg(bias + col + 1);
                if (EPI == 1) {
                    vx += __ldg(res + (size_t)row * N + col);
                    vy += __ldg(res + (size_t)row * N + col + 1);
                } else if (EPI == 2) {
                    vx = 0.5f * vx * (1.f + erff(vx * 0.70710678118654752f));
                    vy = 0.5f * vy * (1.f + erff(vy * 0.70710678118654752f));
                }
                float2 o; o.x = vx; o.y = vy;
                *reinterpret_cast<float2*>(C + (size_t)row * N + col) = o;
            }
        }
    }
}

// ---------------- fused flash attention (tf32 mma, online softmax) ----------------
#define QS_LD 68
#define KS_LD 68
#define VS_LD 72
#define PS_LD 132
#define ATTN_SMEM ((128*QS_LD + 128*KS_LD + 128*VS_LD + 128*PS_LD) * 4)

__global__ void __launch_bounds__(256) attn_kernel(
    const float* __restrict__ q, const float* __restrict__ kg,
    const float* __restrict__ vg, float* __restrict__ ctx)
{
    extern __shared__ unsigned sm[];
    unsigned* Qs = sm;
    unsigned* Ks = Qs + 128 * QS_LD;
    unsigned* Vs = Ks + 128 * KS_LD;
    unsigned* Ps = Vs + 128 * VS_LD;

    const int t = threadIdx.x, lane = t & 31, warp = t >> 5;
    const int g = lane >> 2, t4 = lane & 3;
    const int b = blockIdx.y >> 4, h = blockIdx.y & 15;
    const size_t base = (size_t)b * Sc * Ec + (size_t)h * HDc;
    const float* qp = q  + base + (size_t)blockIdx.x * 128 * Ec;
    const float* kp = kg + base;
    const float* vp = vg + base;

    // load Q tile (128 x 64), tf32-convert into SMEM
    #pragma unroll
    for (int i = 0; i < 8; i++) {
        int lin = t + i*256;
        int r = lin >> 4, c = (lin & 15) * 4;
        float4 x4 = *reinterpret_cast<const float4*>(qp + (size_t)r * Ec + c);
        Qs[r*QS_LD + c    ] = f2tf(x4.x); Qs[r*QS_LD + c + 1] = f2tf(x4.y);
        Qs[r*QS_LD + c + 2] = f2tf(x4.z); Qs[r*QS_LD + c + 3] = f2tf(x4.w);
    }

    float o[8][4];
    #pragma unroll
    for (int ni = 0; ni < 8; ni++)
        #pragma unroll
        for (int c = 0; c < 4; c++) o[ni][c] = 0.f;
    float m0 = -INFINITY, m1 = -INFINITY, l0 = 0.f, l1 = 0.f;
    const int pr0 = warp*16 + g;   // this thread's first local row

    for (int kt = 0; kt < 16; kt++) {
        __syncthreads();
        #pragma unroll
        for (int i = 0; i < 8; i++) {
            int lin = t + i*256;
            int r = lin >> 4, c = (lin & 15) * 4;
            float4 x4 = *reinterpret_cast<const float4*>(kp + (size_t)(kt*128 + r) * Ec + c);
            Ks[r*KS_LD + c    ] = f2tf(x4.x); Ks[r*KS_LD + c + 1] = f2tf(x4.y);
            Ks[r*KS_LD + c + 2] = f2tf(x4.z); Ks[r*KS_LD + c + 3] = f2tf(x4.w);
            float4 y4 = *reinterpret_cast<const float4*>(vp + (size_t)(kt*128 + r) * Ec + c);
            Vs[r*VS_LD + c    ] = f2tf(y4.x); Vs[r*VS_LD + c + 1] = f2tf(y4.y);
            Vs[r*VS_LD + c + 2] = f2tf(y4.z); Vs[r*VS_LD + c + 3] = f2tf(y4.w);
        }
        __syncthreads();

        // S = Q @ K^T  (per warp: 16 rows x 128 cols)
        float sacc[16][4];
        #pragma unroll
        for (int ni = 0; ni < 16; ni++)
            #pragma unroll
            for (int c = 0; c < 4; c++) sacc[ni][c] = 0.f;
        #pragma unroll
        for (int kk = 0; kk < 8; kk++) {
            const int kb = kk * 8;
            unsigned a[4];
            a[0] = Qs[pr0      * QS_LD + kb + t4];
            a[1] = Qs[(pr0+8)  * QS_LD + kb + t4];
            a[2] = Qs[pr0      * QS_LD + kb + t4 + 4];
            a[3] = Qs[(pr0+8)  * QS_LD + kb + t4 + 4];
            #pragma unroll
            for (int ni = 0; ni < 16; ni++) {
                unsigned bb[2];
                int j = ni*8 + g;
                bb[0] = Ks[j*KS_LD + kb + t4];
                bb[1] = Ks[j*KS_LD + kb + t4 + 4];
                mma8(sacc[ni], a, bb);
            }
        }

        // online softmax
        float rm0 = -INFINITY, rm1 = -INFINITY;
        #pragma unroll
        for (int ni = 0; ni < 16; ni++) {
            sacc[ni][0] *= 0.125f; sacc[ni][1] *= 0.125f;
            sacc[ni][2] *= 0.125f; sacc[ni][3] *= 0.125f;
            rm0 = fmaxf(rm0, fmaxf(sacc[ni][0], sacc[ni][1]));
            rm1 = fmaxf(rm1, fmaxf(sacc[ni][2], sacc[ni][3]));
        }
        rm0 = fmaxf(rm0, __shfl_xor_sync(0xffffffffu, rm0, 1));
        rm0 = fmaxf(rm0, __shfl_xor_sync(0xffffffffu, rm0, 2));
        rm1 = fmaxf(rm1, __shfl_xor_sync(0xffffffffu, rm1, 1));
        rm1 = fmaxf(rm1, __shfl_xor_sync(0xffffffffu, rm1, 2));
        const float mn0 = fmaxf(m0, rm0), mn1 = fmaxf(m1, rm1);
        const float al0 = __expf(m0 - mn0), al1 = __expf(m1 - mn1);
        float ps0 = 0.f, ps1 = 0.f;
        #pragma unroll
        for (int ni = 0; ni < 16; ni++) {
            float p0 = __expf(sacc[ni][0] - mn0);
            float p1 = __expf(sacc[ni][1] - mn0);
            float p2 = __expf(sacc[ni][2] - mn1);
            float p3 = __expf(sacc[ni][3] - mn1);
            ps0 += p0 + p1; ps1 += p2 + p3;
            const int col = ni*8 + t4*2;
            Ps[pr0     * PS_LD + col    ] = f2tf(p0);
            Ps[pr0     * PS_LD + col + 1] = f2tf(p1);
            Ps[(pr0+8) * PS_LD + col    ] = f2tf(p2);
            Ps[(pr0+8) * PS_LD + col + 1] = f2tf(p3);
        }
        ps0 += __shfl_xor_sync(0xffffffffu, ps0, 1);
        ps0 += __shfl_xor_sync(0xffffffffu, ps0, 2);
        ps1 += __shfl_xor_sync(0xffffffffu, ps1, 1);
        ps1 += __shfl_xor_sync(0xffffffffu, ps1, 2);
        l0 = l0 * al0 + ps0; l1 = l1 * al1 + ps1;
        m0 = mn0; m1 = mn1;
        #pragma unroll
        for (int ni = 0; ni < 8; ni++) {
            o[ni][0] *= al0; o[ni][1] *= al0;
            o[ni][2] *= al1; o[ni][3] *= al1;
        }
        __syncwarp();

        // O += P @ V   (per warp: 16 x 64, k = 128)
        #pragma unroll
        for (int kk = 0; kk < 16; kk++) {
            const int kb = kk * 8;
            unsigned a[4];
            a[0] = Ps[pr0     * PS_LD + kb + t4];
            a[1] = Ps[(pr0+8) * PS_LD + kb + t4];
            a[2] = Ps[pr0     * PS_LD + kb + t4 + 4];
            a[3] = Ps[(pr0+8) * PS_LD + kb + t4 + 4];
            #pragma unroll
            for (int ni = 0; ni < 8; ni++) {
                unsigned bb[2];
                int d = ni*8 + g;
                bb[0] = Vs[(kb + t4    ) * VS_LD + d];
                bb[1] = Vs[(kb + t4 + 4) * VS_LD + d];
                mma8(o[ni], a, bb);
            }
        }
    }

    const float inv0 = 1.f / l0, inv1 = 1.f / l1;
    float* cp = ctx + base + (size_t)blockIdx.x * 128 * Ec;
    #pragma unroll
    for (int ni = 0; ni < 8; ni++) {
        const int d = ni*8 + t4*2;
        float2 u0; u0.x = o[ni][0] * inv0; u0.y = o[ni][1] * inv0;
        float2 u1; u1.x = o[ni][2] * inv1; u1.y = o[ni][3] * inv1;
        *reinterpret_cast<float2*>(cp + (size_t)pr0     * Ec + d) = u0;
        *reinterpret_cast<float2*>(cp + (size_t)(pr0+8) * Ec + d) = u1;
    }
}

// ---------------- launch ----------------
extern "C" void kernel_launch(void* const* d_in, const int* in_sizes, int n_in,
                              void* d_out, int out_size)
{
    const float* x   = (const float*)d_in[0];
    const float* wq  = (const float*)d_in[1];
    const float* bq  = (const float*)d_in[2];
    const float* wk  = (const float*)d_in[3];
    const float* bk  = (const float*)d_in[4];
    const float* wv  = (const float*)d_in[5];
    const float* bv  = (const float*)d_in[6];
    const float* wo  = (const float*)d_in[7];
    const float* bo  = (const float*)d_in[8];
    const float* w1  = (const float*)d_in[9];
    const float* b1  = (const float*)d_in[10];
    const float* w2  = (const float*)d_in[11];
    const float* b2  = (const float*)d_in[12];
    const float* g1  = (const float*)d_in[13];
    const float* be1 = (const float*)d_in[14];
    const float* g2  = (const float*)d_in[15];
    const float* be2 = (const float*)d_in[16];
    float* out = (float*)d_out;

    float *z0, *q, *k, *v, *ctx, *x1, *z1, *h;
    cudaGetSymbolAddress((void**)&z0,  g_z0);
    cudaGetSymbolAddress((void**)&q,   g_q);
    cudaGetSymbolAddress((void**)&k,   g_k);
    cudaGetSymbolAddress((void**)&v,   g_v);
    cudaGetSymbolAddress((void**)&ctx, g_ctx);
    cudaGetSymbolAddress((void**)&x1,  g_x1);
    cudaGetSymbolAddress((void**)&z1,  g_z1);
    cudaGetSymbolAddress((void**)&h,   g_h);

    cudaFuncSetAttribute(attn_kernel, cudaFuncAttributeMaxDynamicSharedMemorySize, ATTN_SMEM);

    ln_kernel<<<TOK, 256>>>(x, g1, be1, z0);
    gemm_kernel<0><<<dim3(Ec/128, TOK/128), 256>>>(z0, wq, bq, nullptr, q, TOK, Ec, Ec);
    gemm_kernel<0><<<dim3(Ec/128, TOK/128), 256>>>(z0, wk, bk, nullptr, k, TOK, Ec, Ec);
    gemm_kernel<0><<<dim3(Ec/128, TOK/128), 256>>>(z0, wv, bv, nullptr, v, TOK, Ec, Ec);
    attn_kernel<<<dim3(Sc/128, Bc*Hc), 256, ATTN_SMEM>>>(q, k, v, ctx);
    gemm_kernel<1><<<dim3(Ec/128, TOK/128), 256>>>(ctx, wo, bo, x, x1, TOK, Ec, Ec);
    ln_kernel<<<TOK, 256>>>(x1, g2, be2, z1);
    gemm_kernel<2><<<dim3(MLPc/128, TOK/128), 256>>>(z1, w1, b1, nullptr, h, TOK, MLPc, Ec);
    gemm_kernel<1><<<dim3(Ec/128, TOK/128), 256>>>(h, w2, b2, x1, out, TOK, Ec, MLPc);
}

// round 3
// speedup vs baseline: 1.2583x; 1.2583x over previous
#include <cuda_runtime.h>
#include <cstdint>
#include <math.h>

#define Bc   2
#define Sc   2048
#define TOK  4096
#define Ec   1024
#define Hc   16
#define HDc  64
#define MLPc 4096

// ---------------- scratch (no allocations allowed) ----------------
__device__ float g_z0[(size_t)TOK * Ec];
__device__ float g_q [(size_t)TOK * Ec];
__device__ float g_k [(size_t)TOK * Ec];
__device__ float g_v [(size_t)TOK * Ec];
__device__ float g_ctx[(size_t)TOK * Ec];
__device__ float g_x1[(size_t)TOK * Ec];
__device__ float g_z1[(size_t)TOK * Ec];
__device__ float g_h [(size_t)TOK * MLPc];
__device__ float g_wqT[(size_t)Ec * Ec];
__device__ float g_wkT[(size_t)Ec * Ec];
__device__ float g_wvT[(size_t)Ec * Ec];
__device__ float g_woT[(size_t)Ec * Ec];
__device__ float g_w1T[(size_t)Ec * MLPc];
__device__ float g_w2T[(size_t)MLPc * Ec];

// ---------------- helpers ----------------
__device__ __forceinline__ unsigned f2tf(float f) {
    unsigned r;
    asm("cvt.rna.tf32.f32 %0, %1;" : "=r"(r) : "f"(f));
    return r;
}
// round float to tf32 value, keep as float
__device__ __forceinline__ float tfround(float f) {
    return __uint_as_float(f2tf(f));
}

__device__ __forceinline__ uint32_t smem_u32(const void* p) {
    uint32_t a;
    asm("{ .reg .u64 t; cvta.to.shared.u64 t, %1; cvt.u32.u64 %0, t; }" : "=r"(a) : "l"(p));
    return a;
}

__device__ __forceinline__ void mma8(float c[4], const unsigned a[4], const unsigned b[2]) {
    asm volatile(
        "mma.sync.aligned.m16n8k8.row.col.f32.tf32.tf32.f32 "
        "{%0,%1,%2,%3}, {%4,%5,%6,%7}, {%8,%9}, {%0,%1,%2,%3};\n"
        : "+f"(c[0]), "+f"(c[1]), "+f"(c[2]), "+f"(c[3])
        : "r"(a[0]), "r"(a[1]), "r"(a[2]), "r"(a[3]),
          "r"(b[0]), "r"(b[1]));
}

// ---------------- weight transpose + tf32 round: out[C][R] = tf32(in[R][C]) ------
__global__ void __launch_bounds__(256) transpose_kernel(
    const float* __restrict__ in, float* __restrict__ out, int R, int C)
{
    __shared__ float tile[32][33];
    const int bx = blockIdx.x * 32, by = blockIdx.y * 32;
    const int tx = threadIdx.x & 31, ty = threadIdx.x >> 5;
    #pragma unroll
    for (int i = 0; i < 32; i += 8)
        tile[ty + i][tx] = tfround(in[(size_t)(by + ty + i) * C + bx + tx]);
    __syncthreads();
    #pragma unroll
    for (int i = 0; i < 32; i += 8)
        out[(size_t)(bx + ty + i) * R + by + tx] = tile[tx][ty + i];
}

// ---------------- LayerNorm (fp32 exact, tf32-rounded output) ----------------
__global__ void __launch_bounds__(256) ln_kernel(
    const float* __restrict__ x, const float* __restrict__ gam,
    const float* __restrict__ bet, float* __restrict__ y)
{
    const int row = blockIdx.x, t = threadIdx.x;
    const float4* xr = reinterpret_cast<const float4*>(x + (size_t)row * Ec);
    float4 v = xr[t];
    float s  = v.x + v.y + v.z + v.w;
    float ss = v.x*v.x + v.y*v.y + v.z*v.z + v.w*v.w;
    #pragma unroll
    for (int o = 16; o; o >>= 1) {
        s  += __shfl_xor_sync(0xffffffffu, s,  o);
        ss += __shfl_xor_sync(0xffffffffu, ss, o);
    }
    __shared__ float rs[8], rss[8];
    if ((t & 31) == 0) { rs[t >> 5] = s; rss[t >> 5] = ss; }
    __syncthreads();
    if (t < 32) {
        float a = (t < 8) ? rs[t]  : 0.f;
        float b = (t < 8) ? rss[t] : 0.f;
        #pragma unroll
        for (int o = 4; o; o >>= 1) {
            a += __shfl_xor_sync(0xffffffffu, a, o);
            b += __shfl_xor_sync(0xffffffffu, b, o);
        }
        if (t == 0) { rs[0] = a; rss[0] = b; }
    }
    __syncthreads();
    const float mu   = rs[0]  * (1.f / Ec);
    const float var  = rss[0] * (1.f / Ec) - mu * mu;
    const float rstd = rsqrtf(var + 1e-5f);
    float4 gv = reinterpret_cast<const float4*>(gam)[t];
    float4 bv = reinterpret_cast<const float4*>(bet)[t];
    float4 o;
    o.x = tfround((v.x - mu) * rstd * gv.x + bv.x);
    o.y = tfround((v.y - mu) * rstd * gv.y + bv.y);
    o.z = tfround((v.z - mu) * rstd * gv.z + bv.z);
    o.w = tfround((v.w - mu) * rstd * gv.w + bv.w);
    reinterpret_cast<float4*>(y + (size_t)row * Ec)[t] = o;
}

// ---------------- TF32 GEMM, cp.async multistage: C = A @ BT^T + bias (+res/gelu)
// A[M,K] K-major (tf32-rounded floats), BT[N,K] K-major (tf32-rounded floats).
// Block tile 128x128, warp tile 64x64 (2x2 warps), k-tile 16, 4 stages.
#define GS_STRIDE 20          // words per 16-float row (16 + 4 pad)
#define GS_STAGE  (128 * GS_STRIDE)          // words per operand stage
#define SMEM_GEMM (2 * 4 * GS_STAGE * 4)     // bytes = 81920

template <int EPI>  // 0 = bias(->tf32), 1 = bias+res (fp32), 2 = bias+gelu(->tf32)
__global__ void __launch_bounds__(128, 2) tc_gemm(
    const float* __restrict__ A, const float* __restrict__ BT,
    const float* __restrict__ bias, const float* __restrict__ res,
    float* __restrict__ C, int M, int N, int K)
{
    extern __shared__ float smem[];
    float* As = smem;                 // [4][128][20]
    float* Bs = smem + 4 * GS_STAGE;  // [4][128][20]

    const int t    = threadIdx.x;
    const int lane = t & 31, warp = t >> 5;
    const int wm = warp >> 1, wn = warp & 1;
    const int g  = lane >> 2, t4 = lane & 3;
    const int bm = blockIdx.y * 128, bn = blockIdx.x * 128;
    const float* Ap = A  + (size_t)bm * K;
    const float* Bp = BT + (size_t)bn * K;
    const int NK = K >> 4;

    const int r0 = t >> 2;            // base row for loads (+32*i)
    const int c4 = (t & 3) * 4;       // k offset (floats)

    float acc[4][8][4];
    #pragma unroll
    for (int mi = 0; mi < 4; mi++)
        #pragma unroll
        for (int ni = 0; ni < 8; ni++)
            #pragma unroll
            for (int c = 0; c < 4; c++) acc[mi][ni][c] = 0.f;

    const uint32_t asb = smem_u32(As);
    const uint32_t bsb = smem_u32(Bs);

    // prologue: stages 0..2
    #pragma unroll
    for (int s = 0; s < 3; s++) {
        const int k0 = s * 16 + c4;
        const uint32_t ab = asb + (s * GS_STAGE) * 4;
        const uint32_t bb = bsb + (s * GS_STAGE) * 4;
        #pragma unroll
        for (int i = 0; i < 4; i++) {
            const int row = r0 + i * 32;
            asm volatile("cp.async.cg.shared.global [%0], [%1], 16;\n"
                         :: "r"(ab + (row * GS_STRIDE + c4) * 4),
                            "l"(Ap + (size_t)row * K + k0));
            asm volatile("cp.async.cg.shared.global [%0], [%1], 16;\n"
                         :: "r"(bb + (row * GS_STRIDE + c4) * 4),
                            "l"(Bp + (size_t)row * K + k0));
        }
        asm volatile("cp.async.commit_group;\n" ::: "memory");
    }

    for (int kt = 0; kt < NK; kt++) {
        asm volatile("cp.async.wait_group 2;\n" ::: "memory");
        __syncthreads();
        const int st = kt & 3;
        const float* as = As + st * GS_STAGE;
        const float* bs = Bs + st * GS_STAGE;
        #pragma unroll
        for (int kb = 0; kb < 16; kb += 8) {
            unsigned af[4][4], bf[8][2];
            #pragma unroll
            for (int mi = 0; mi < 4; mi++) {
                const float* ar = as + (wm*64 + mi*16 + g) * GS_STRIDE + kb + t4;
                af[mi][0] = __float_as_uint(ar[0]);
                af[mi][1] = __float_as_uint(ar[8 * GS_STRIDE]);
                af[mi][2] = __float_as_uint(ar[4]);
                af[mi][3] = __float_as_uint(ar[8 * GS_STRIDE + 4]);
            }
            #pragma unroll
            for (int ni = 0; ni < 8; ni++) {
                const float* br = bs + (wn*64 + ni*8 + g) * GS_STRIDE + kb + t4;
                bf[ni][0] = __float_as_uint(br[0]);
                bf[ni][1] = __float_as_uint(br[4]);
            }
            #pragma unroll
            for (int mi = 0; mi < 4; mi++)
                #pragma unroll
                for (int ni = 0; ni < 8; ni++)
                    mma8(acc[mi][ni], af[mi], bf[ni]);
        }
        // prefetch stage kt+3 (writes a stage no warp is reading this iter)
        const int pf = kt + 3;
        if (pf < NK) {
            const int ps = pf & 3;
            const int k0 = pf * 16 + c4;
            const uint32_t ab = asb + (ps * GS_STAGE) * 4;
            const uint32_t bb = bsb + (ps * GS_STAGE) * 4;
            #pragma unroll
            for (int i = 0; i < 4; i++) {
                const int row = r0 + i * 32;
                asm volatile("cp.async.cg.shared.global [%0], [%1], 16;\n"
                             :: "r"(ab + (row * GS_STRIDE + c4) * 4),
                                "l"(Ap + (size_t)row * K + k0));
                asm volatile("cp.async.cg.shared.global [%0], [%1], 16;\n"
                             :: "r"(bb + (row * GS_STRIDE + c4) * 4),
                                "l"(Bp + (size_t)row * K + k0));
            }
        }
        asm volatile("cp.async.commit_group;\n" ::: "memory");
    }

    // epilogue
    #pragma unroll
    for (int mi = 0; mi < 4; mi++) {
        #pragma unroll
        for (int half = 0; half < 2; half++) {
            const int row = bm + wm*64 + mi*16 + g + half*8;
            #pragma unroll
            for (int ni = 0; ni < 8; ni++) {
                const int col = bn + wn*64 + ni*8 + t4*2;
                float vx = acc[mi][ni][half*2 + 0] + __ldg(bias + col);
                float vy = acc[mi][ni][half*2 + 1] + __ldg(bias + col + 1);
                if (EPI == 1) {
                    vx += __ldg(res + (size_t)row * N + col);
                    vy += __ldg(res + (size_t)row * N + col + 1);
                } else if (EPI == 2) {
                    vx = 0.5f * vx * (1.f + erff(vx * 0.70710678118654752f));
                    vy = 0.5f * vy * (1.f + erff(vy * 0.70710678118654752f));
                    vx = tfround(vx); vy = tfround(vy);
                } else {
                    vx = tfround(vx); vy = tfround(vy);
                }
                float2 o; o.x = vx; o.y = vy;
                *reinterpret_cast<float2*>(C + (size_t)row * N + col) = o;
            }
        }
    }
}

// ---------------- fused flash attention (legacy tf32 mma, online softmax) ----------
#define QS_LD 68
#define KS_LD 68
#define VS_LD 72
#define PS_LD 132
#define ATTN_SMEM ((128*QS_LD + 128*KS_LD + 128*VS_LD + 128*PS_LD) * 4)

__global__ void __launch_bounds__(256) attn_kernel(
    const float* __restrict__ q, const float* __restrict__ kg,
    const float* __restrict__ vg, float* __restrict__ ctx)
{
    extern __shared__ unsigned sm[];
    unsigned* Qs = sm;
    unsigned* Ks = Qs + 128 * QS_LD;
    unsigned* Vs = Ks + 128 * KS_LD;
    unsigned* Ps = Vs + 128 * VS_LD;

    const int t = threadIdx.x, lane = t & 31, warp = t >> 5;
    const int g = lane >> 2, t4 = lane & 3;
    const int b = blockIdx.y >> 4, h = blockIdx.y & 15;
    const size_t base = (size_t)b * Sc * Ec + (size_t)h * HDc;
    const float* qp = q  + base + (size_t)blockIdx.x * 128 * Ec;
    const float* kp = kg + base;
    const float* vp = vg + base;

    #pragma unroll
    for (int i = 0; i < 8; i++) {
        int lin = t + i*256;
        int r = lin >> 4, c = (lin & 15) * 4;
        float4 x4 = *reinterpret_cast<const float4*>(qp + (size_t)r * Ec + c);
        Qs[r*QS_LD + c    ] = f2tf(x4.x); Qs[r*QS_LD + c + 1] = f2tf(x4.y);
        Qs[r*QS_LD + c + 2] = f2tf(x4.z); Qs[r*QS_LD + c + 3] = f2tf(x4.w);
    }

    float o[8][4];
    #pragma unroll
    for (int ni = 0; ni < 8; ni++)
        #pragma unroll
        for (int c = 0; c < 4; c++) o[ni][c] = 0.f;
    float m0 = -INFINITY, m1 = -INFINITY, l0 = 0.f, l1 = 0.f;
    const int pr0 = warp*16 + g;

    for (int kt = 0; kt < 16; kt++) {
        __syncthreads();
        #pragma unroll
        for (int i = 0; i < 8; i++) {
            int lin = t + i*256;
            int r = lin >> 4, c = (lin & 15) * 4;
            float4 x4 = *reinterpret_cast<const float4*>(kp + (size_t)(kt*128 + r) * Ec + c);
            Ks[r*KS_LD + c    ] = f2tf(x4.x); Ks[r*KS_LD + c + 1] = f2tf(x4.y);
            Ks[r*KS_LD + c + 2] = f2tf(x4.z); Ks[r*KS_LD + c + 3] = f2tf(x4.w);
            float4 y4 = *reinterpret_cast<const float4*>(vp + (size_t)(kt*128 + r) * Ec + c);
            Vs[r*VS_LD + c    ] = f2tf(y4.x); Vs[r*VS_LD + c + 1] = f2tf(y4.y);
            Vs[r*VS_LD + c + 2] = f2tf(y4.z); Vs[r*VS_LD + c + 3] = f2tf(y4.w);
        }
        __syncthreads();

        float sacc[16][4];
        #pragma unroll
        for (int ni = 0; ni < 16; ni++)
            #pragma unroll
            for (int c = 0; c < 4; c++) sacc[ni][c] = 0.f;
        #pragma unroll
        for (int kk = 0; kk < 8; kk++) {
            const int kb = kk * 8;
            unsigned a[4];
            a[0] = Qs[pr0      * QS_LD + kb + t4];
            a[1] = Qs[(pr0+8)  * QS_LD + kb + t4];
            a[2] = Qs[pr0      * QS_LD + kb + t4 + 4];
            a[3] = Qs[(pr0+8)  * QS_LD + kb + t4 + 4];
            #pragma unroll
            for (int ni = 0; ni < 16; ni++) {
                unsigned bb[2];
                int j = ni*8 + g;
                bb[0] = Ks[j*KS_LD + kb + t4];
                bb[1] = Ks[j*KS_LD + kb + t4 + 4];
                mma8(sacc[ni], a, bb);
            }
        }

        float rm0 = -INFINITY, rm1 = -INFINITY;
        #pragma unroll
        for (int ni = 0; ni < 16; ni++) {
            sacc[ni][0] *= 0.125f; sacc[ni][1] *= 0.125f;
            sacc[ni][2] *= 0.125f; sacc[ni][3] *= 0.125f;
            rm0 = fmaxf(rm0, fmaxf(sacc[ni][0], sacc[ni][1]));
            rm1 = fmaxf(rm1, fmaxf(sacc[ni][2], sacc[ni][3]));
        }
        rm0 = fmaxf(rm0, __shfl_xor_sync(0xffffffffu, rm0, 1));
        rm0 = fmaxf(rm0, __shfl_xor_sync(0xffffffffu, rm0, 2));
        rm1 = fmaxf(rm1, __shfl_xor_sync(0xffffffffu, rm1, 1));
        rm1 = fmaxf(rm1, __shfl_xor_sync(0xffffffffu, rm1, 2));
        const float mn0 = fmaxf(m0, rm0), mn1 = fmaxf(m1, rm1);
        const float al0 = __expf(m0 - mn0), al1 = __expf(m1 - mn1);
        float ps0 = 0.f, ps1 = 0.f;
        #pragma unroll
        for (int ni = 0; ni < 16; ni++) {
            float p0 = __expf(sacc[ni][0] - mn0);
            float p1 = __expf(sacc[ni][1] - mn0);
            float p2 = __expf(sacc[ni][2] - mn1);
            float p3 = __expf(sacc[ni][3] - mn1);
            ps0 += p0 + p1; ps1 += p2 + p3;
            const int col = ni*8 + t4*2;
            Ps[pr0     * PS_LD + col    ] = f2tf(p0);
            Ps[pr0     * PS_LD + col + 1] = f2tf(p1);
            Ps[(pr0+8) * PS_LD + col    ] = f2tf(p2);
            Ps[(pr0+8) * PS_LD + col + 1] = f2tf(p3);
        }
        ps0 += __shfl_xor_sync(0xffffffffu, ps0, 1);
        ps0 += __shfl_xor_sync(0xffffffffu, ps0, 2);
        ps1 += __shfl_xor_sync(0xffffffffu, ps1, 1);
        ps1 += __shfl_xor_sync(0xffffffffu, ps1, 2);
        l0 = l0 * al0 + ps0; l1 = l1 * al1 + ps1;
        m0 = mn0; m1 = mn1;
        #pragma unroll
        for (int ni = 0; ni < 8; ni++) {
            o[ni][0] *= al0; o[ni][1] *= al0;
            o[ni][2] *= al1; o[ni][3] *= al1;
        }
        __syncwarp();

        #pragma unroll
        for (int kk = 0; kk < 16; kk++) {
            const int kb = kk * 8;
            unsigned a[4];
            a[0] = Ps[pr0     * PS_LD + kb + t4];
            a[1] = Ps[(pr0+8) * PS_LD + kb + t4];
            a[2] = Ps[pr0     * PS_LD + kb + t4 + 4];
            a[3] = Ps[(pr0+8) * PS_LD + kb + t4 + 4];
            #pragma unroll
            for (int ni = 0; ni < 8; ni++) {
                unsigned bb[2];
                int d = ni*8 + g;
                bb[0] = Vs[(kb + t4    ) * VS_LD + d];
                bb[1] = Vs[(kb + t4 + 4) * VS_LD + d];
                mma8(o[ni], a, bb);
            }
        }
    }

    const float inv0 = 1.f / l0, inv1 = 1.f / l1;
    float* cp = ctx + base + (size_t)blockIdx.x * 128 * Ec;
    #pragma unroll
    for (int ni = 0; ni < 8; ni++) {
        const int d = ni*8 + t4*2;
        float2 u0; u0.x = tfround(o[ni][0] * inv0); u0.y = tfround(o[ni][1] * inv0);
        float2 u1; u1.x = tfround(o[ni][2] * inv1); u1.y = tfround(o[ni][3] * inv1);
        *reinterpret_cast<float2*>(cp + (size_t)pr0     * Ec + d) = u0;
        *reinterpret_cast<float2*>(cp + (size_t)(pr0+8) * Ec + d) = u1;
    }
}

// ---------------- launch ----------------
extern "C" void kernel_launch(void* const* d_in, const int* in_sizes, int n_in,
                              void* d_out, int out_size)
{
    const float* x   = (const float*)d_in[0];
    const float* wq  = (const float*)d_in[1];
    const float* bq  = (const float*)d_in[2];
    const float* wk  = (const float*)d_in[3];
    const float* bk  = (const float*)d_in[4];
    const float* wv  = (const float*)d_in[5];
    const float* bv  = (const float*)d_in[6];
    const float* wo  = (const float*)d_in[7];
    const float* bo  = (const float*)d_in[8];
    const float* w1  = (const float*)d_in[9];
    const float* b1  = (const float*)d_in[10];
    const float* w2  = (const float*)d_in[11];
    const float* b2  = (const float*)d_in[12];
    const float* g1  = (const float*)d_in[13];
    const float* be1 = (const float*)d_in[14];
    const float* g2  = (const float*)d_in[15];
    const float* be2 = (const float*)d_in[16];
    float* out = (float*)d_out;

    float *z0, *q, *k, *v, *ctx, *x1, *z1, *h;
    float *wqT, *wkT, *wvT, *woT, *w1T, *w2T;
    cudaGetSymbolAddress((void**)&z0,  g_z0);
    cudaGetSymbolAddress((void**)&q,   g_q);
    cudaGetSymbolAddress((void**)&k,   g_k);
    cudaGetSymbolAddress((void**)&v,   g_v);
    cudaGetSymbolAddress((void**)&ctx, g_ctx);
    cudaGetSymbolAddress((void**)&x1,  g_x1);
    cudaGetSymbolAddress((void**)&z1,  g_z1);
    cudaGetSymbolAddress((void**)&h,   g_h);
    cudaGetSymbolAddress((void**)&wqT, g_wqT);
    cudaGetSymbolAddress((void**)&wkT, g_wkT);
    cudaGetSymbolAddress((void**)&wvT, g_wvT);
    cudaGetSymbolAddress((void**)&woT, g_woT);
    cudaGetSymbolAddress((void**)&w1T, g_w1T);
    cudaGetSymbolAddress((void**)&w2T, g_w2T);

    cudaFuncSetAttribute(attn_kernel, cudaFuncAttributeMaxDynamicSharedMemorySize, ATTN_SMEM);
    cudaFuncSetAttribute(tc_gemm<0>, cudaFuncAttributeMaxDynamicSharedMemorySize, SMEM_GEMM);
    cudaFuncSetAttribute(tc_gemm<1>, cudaFuncAttributeMaxDynamicSharedMemorySize, SMEM_GEMM);
    cudaFuncSetAttribute(tc_gemm<2>, cudaFuncAttributeMaxDynamicSharedMemorySize, SMEM_GEMM);

    // weight transposes + tf32 rounding (part of the timed graph; ~20us)
    transpose_kernel<<<dim3(Ec/32,  Ec/32),   256>>>(wq, wqT, Ec, Ec);
    transpose_kernel<<<dim3(Ec/32,  Ec/32),   256>>>(wk, wkT, Ec, Ec);
    transpose_kernel<<<dim3(Ec/32,  Ec/32),   256>>>(wv, wvT, Ec, Ec);
    transpose_kernel<<<dim3(Ec/32,  Ec/32),   256>>>(wo, woT, Ec, Ec);
    transpose_kernel<<<dim3(MLPc/32, Ec/32),  256>>>(w1, w1T, Ec, MLPc);
    transpose_kernel<<<dim3(Ec/32,  MLPc/32), 256>>>(w2, w2T, MLPc, Ec);

    ln_kernel<<<TOK, 256>>>(x, g1, be1, z0);
    tc_gemm<0><<<dim3(Ec/128,  TOK/128), 128, SMEM_GEMM>>>(z0,  wqT, bq, nullptr, q,   TOK, Ec,   Ec);
    tc_gemm<0><<<dim3(Ec/128,  TOK/128), 128, SMEM_GEMM>>>(z0,  wkT, bk, nullptr, k,   TOK, Ec,   Ec);
    tc_gemm<0><<<dim3(Ec/128,  TOK/128), 128, SMEM_GEMM>>>(z0,  wvT, bv, nullptr, v,   TOK, Ec,   Ec);
    attn_kernel<<<dim3(Sc/128, Bc*Hc), 256, ATTN_SMEM>>>(q, k, v, ctx);
    tc_gemm<1><<<dim3(Ec/128,  TOK/128), 128, SMEM_GEMM>>>(ctx, woT, bo, x,  x1,  TOK, Ec,   Ec);
    ln_kernel<<<TOK, 256>>>(x1, g2, be2, z1);
    tc_gemm<2><<<dim3(MLPc/128, TOK/128), 128, SMEM_GEMM>>>(z1, w1T, b1, nullptr, h,  TOK, MLPc, Ec);
    tc_gemm<1><<<dim3(Ec/128,  TOK/128), 128, SMEM_GEMM>>>(h,  w2T, b2, x1, out, TOK, Ec,   MLPc);
}

// round 4
// speedup vs baseline: 1.3526x; 1.0749x over previous
#include <cuda_runtime.h>
#include <cstdint>
#include <math.h>

#define Bc   2
#define Sc   2048
#define TOK  4096
#define Ec   1024
#define Hc   16
#define HDc  64
#define MLPc 4096

// ---------------- scratch (no allocations allowed) ----------------
__device__ float g_z0[(size_t)TOK * Ec];
__device__ float g_q [(size_t)TOK * Ec];
__device__ float g_k [(size_t)TOK * Ec];
__device__ float g_v [(size_t)TOK * Ec];
__device__ float g_ctx[(size_t)TOK * Ec];
__device__ float g_x1[(size_t)TOK * Ec];
__device__ float g_z1[(size_t)TOK * Ec];
__device__ float g_h [(size_t)TOK * MLPc];
__device__ float g_wqkvT[(size_t)3 * Ec * Ec];
__device__ float g_woT[(size_t)Ec * Ec];
__device__ float g_w1T[(size_t)Ec * MLPc];
__device__ float g_w2T[(size_t)MLPc * Ec];

// ---------------- helpers ----------------
__device__ __forceinline__ unsigned f2tf(float f) {
    unsigned r;
    asm("cvt.rna.tf32.f32 %0, %1;" : "=r"(r) : "f"(f));
    return r;
}
__device__ __forceinline__ float tfround(float f) {
    return __uint_as_float(f2tf(f));
}
__device__ __forceinline__ uint32_t smem_u32(const void* p) {
    uint32_t a;
    asm("{ .reg .u64 t; cvta.to.shared.u64 t, %1; cvt.u32.u64 %0, t; }" : "=r"(a) : "l"(p));
    return a;
}
__device__ __forceinline__ void cp16(uint32_t d, const void* s) {
    asm volatile("cp.async.cg.shared.global [%0], [%1], 16;\n" :: "r"(d), "l"(s));
}
__device__ __forceinline__ void cp_commit() {
    asm volatile("cp.async.commit_group;\n" ::: "memory");
}
#define CP_WAIT(n) asm volatile("cp.async.wait_group %0;\n" :: "n"(n) : "memory")

__device__ __forceinline__ void mma8(float c[4], const unsigned a[4], const unsigned b[2]) {
    asm volatile(
        "mma.sync.aligned.m16n8k8.row.col.f32.tf32.tf32.f32 "
        "{%0,%1,%2,%3}, {%4,%5,%6,%7}, {%8,%9}, {%0,%1,%2,%3};\n"
        : "+f"(c[0]), "+f"(c[1]), "+f"(c[2]), "+f"(c[3])
        : "r"(a[0]), "r"(a[1]), "r"(a[2]), "r"(a[3]),
          "r"(b[0]), "r"(b[1]));
}

// ---------------- weight transposes (+ tf32 rounding) ----------------
__global__ void __launch_bounds__(256) transpose4_kernel(
    const float* __restrict__ i0, const float* __restrict__ i1,
    const float* __restrict__ i2, const float* __restrict__ i3,
    float* __restrict__ o0, float* __restrict__ o1,
    float* __restrict__ o2, float* __restrict__ o3)
{
    const float* in  = (blockIdx.z == 0) ? i0 : (blockIdx.z == 1) ? i1 : (blockIdx.z == 2) ? i2 : i3;
    float*       out = (blockIdx.z == 0) ? o0 : (blockIdx.z == 1) ? o1 : (blockIdx.z == 2) ? o2 : o3;
    __shared__ float tile[32][33];
    const int bx = blockIdx.x * 32, by = blockIdx.y * 32;
    const int tx = threadIdx.x & 31, ty = threadIdx.x >> 5;
    #pragma unroll
    for (int i = 0; i < 32; i += 8)
        tile[ty + i][tx] = tfround(in[(size_t)(by + ty + i) * Ec + bx + tx]);
    __syncthreads();
    #pragma unroll
    for (int i = 0; i < 32; i += 8)
        out[(size_t)(bx + ty + i) * Ec + by + tx] = tile[tx][ty + i];
}

__global__ void __launch_bounds__(256) transpose_kernel(
    const float* __restrict__ in, float* __restrict__ out, int R, int C)
{
    __shared__ float tile[32][33];
    const int bx = blockIdx.x * 32, by = blockIdx.y * 32;
    const int tx = threadIdx.x & 31, ty = threadIdx.x >> 5;
    #pragma unroll
    for (int i = 0; i < 32; i += 8)
        tile[ty + i][tx] = tfround(in[(size_t)(by + ty + i) * C + bx + tx]);
    __syncthreads();
    #pragma unroll
    for (int i = 0; i < 32; i += 8)
        out[(size_t)(bx + ty + i) * R + by + tx] = tile[tx][ty + i];
}

// ---------------- LayerNorm (fp32 exact, tf32-rounded output) ----------------
__global__ void __launch_bounds__(256) ln_kernel(
    const float* __restrict__ x, const float* __restrict__ gam,
    const float* __restrict__ bet, float* __restrict__ y)
{
    const int row = blockIdx.x, t = threadIdx.x;
    const float4* xr = reinterpret_cast<const float4*>(x + (size_t)row * Ec);
    float4 v = xr[t];
    float s  = v.x + v.y + v.z + v.w;
    float ss = v.x*v.x + v.y*v.y + v.z*v.z + v.w*v.w;
    #pragma unroll
    for (int o = 16; o; o >>= 1) {
        s  += __shfl_xor_sync(0xffffffffu, s,  o);
        ss += __shfl_xor_sync(0xffffffffu, ss, o);
    }
    __shared__ float rs[8], rss[8];
    if ((t & 31) == 0) { rs[t >> 5] = s; rss[t >> 5] = ss; }
    __syncthreads();
    if (t < 32) {
        float a = (t < 8) ? rs[t]  : 0.f;
        float b = (t < 8) ? rss[t] : 0.f;
        #pragma unroll
        for (int o = 4; o; o >>= 1) {
            a += __shfl_xor_sync(0xffffffffu, a, o);
            b += __shfl_xor_sync(0xffffffffu, b, o);
        }
        if (t == 0) { rs[0] = a; rss[0] = b; }
    }
    __syncthreads();
    const float mu   = rs[0]  * (1.f / Ec);
    const float var  = rss[0] * (1.f / Ec) - mu * mu;
    const float rstd = rsqrtf(var + 1e-5f);
    float4 gv = reinterpret_cast<const float4*>(gam)[t];
    float4 bv = reinterpret_cast<const float4*>(bet)[t];
    float4 o;
    o.x = tfround((v.x - mu) * rstd * gv.x + bv.x);
    o.y = tfround((v.y - mu) * rstd * gv.y + bv.y);
    o.z = tfround((v.z - mu) * rstd * gv.z + bv.z);
    o.w = tfround((v.w - mu) * rstd * gv.w + bv.w);
    reinterpret_cast<float4*>(y + (size_t)row * Ec)[t] = o;
}

// ---------------- TF32 GEMM mainloop (5-stage cp.async, 128x128, 4 warps) ------
#define GS_STRIDE 20
#define GS_STAGE  (128 * GS_STRIDE)
#define N_STAGES  5
#define SMEM_GEMM (2 * N_STAGES * GS_STAGE * 4)   // 102400 bytes

__device__ __forceinline__ void gemm_mainloop(
    const float* __restrict__ Ap, const float* __restrict__ Bp, int K,
    float* smem, float acc[4][8][4])
{
    const int t    = threadIdx.x;
    const int lane = t & 31, warp = t >> 5;
    const int wm = warp >> 1, wn = warp & 1;
    const int g  = lane >> 2, t4 = lane & 3;
    const int r0 = t >> 2;
    const int c4 = (t & 3) * 4;
    const int NK = K >> 4;

    const uint32_t asb = smem_u32(smem);
    const uint32_t bsb = asb + N_STAGES * GS_STAGE * 4;

    #pragma unroll
    for (int s = 0; s < 4; s++) {
        const int k0 = s * 16 + c4;
        const uint32_t ab = asb + (s * GS_STAGE) * 4;
        const uint32_t bb = bsb + (s * GS_STAGE) * 4;
        #pragma unroll
        for (int i = 0; i < 4; i++) {
            const int row = r0 + i * 32;
            cp16(ab + (row * GS_STRIDE + c4) * 4, Ap + (size_t)row * K + k0);
            cp16(bb + (row * GS_STRIDE + c4) * 4, Bp + (size_t)row * K + k0);
        }
        cp_commit();
    }

    int st = 0;
    for (int kt = 0; kt < NK; kt++) {
        CP_WAIT(3);
        __syncthreads();
        const float* as = smem + st * GS_STAGE;
        const float* bs = smem + N_STAGES * GS_STAGE + st * GS_STAGE;
        #pragma unroll
        for (int kb = 0; kb < 16; kb += 8) {
            unsigned af[4][4], bf[8][2];
            #pragma unroll
            for (int mi = 0; mi < 4; mi++) {
                const float* ar = as + (wm*64 + mi*16 + g) * GS_STRIDE + kb + t4;
                af[mi][0] = __float_as_uint(ar[0]);
                af[mi][1] = __float_as_uint(ar[8 * GS_STRIDE]);
                af[mi][2] = __float_as_uint(ar[4]);
                af[mi][3] = __float_as_uint(ar[8 * GS_STRIDE + 4]);
            }
            #pragma unroll
            for (int ni = 0; ni < 8; ni++) {
                const float* br = bs + (wn*64 + ni*8 + g) * GS_STRIDE + kb + t4;
                bf[ni][0] = __float_as_uint(br[0]);
                bf[ni][1] = __float_as_uint(br[4]);
            }
            #pragma unroll
            for (int mi = 0; mi < 4; mi++)
                #pragma unroll
                for (int ni = 0; ni < 8; ni++)
                    mma8(acc[mi][ni], af[mi], bf[ni]);
        }
        const int pf = kt + 4;
        if (pf < NK) {
            int ps = st + 4; if (ps >= N_STAGES) ps -= N_STAGES;
            const int k0 = pf * 16 + c4;
            const uint32_t ab = asb + (ps * GS_STAGE) * 4;
            const uint32_t bb = bsb + (ps * GS_STAGE) * 4;
            #pragma unroll
            for (int i = 0; i < 4; i++) {
                const int row = r0 + i * 32;
                cp16(ab + (row * GS_STRIDE + c4) * 4, Ap + (size_t)row * K + k0);
                cp16(bb + (row * GS_STRIDE + c4) * 4, Bp + (size_t)row * K + k0);
            }
        }
        cp_commit();
        st++; if (st == N_STAGES) st = 0;
    }
}

// EPI: 0 = bias(->tf32), 1 = bias+res (fp32), 2 = bias+gelu(->tf32)
template <int EPI>
__global__ void __launch_bounds__(128, 2) tc_gemm(
    const float* __restrict__ A, const float* __restrict__ BT,
    const float* __restrict__ bias, const float* __restrict__ res,
    float* __restrict__ C, int M, int N, int K)
{
    extern __shared__ float smem[];
    const int t = threadIdx.x;
    const int lane = t & 31, warp = t >> 5;
    const int wm = warp >> 1, wn = warp & 1;
    const int g  = lane >> 2, t4 = lane & 3;
    const int bm = blockIdx.y * 128, bn = blockIdx.x * 128;

    float acc[4][8][4];
    #pragma unroll
    for (int mi = 0; mi < 4; mi++)
        #pragma unroll
        for (int ni = 0; ni < 8; ni++)
            #pragma unroll
            for (int c = 0; c < 4; c++) acc[mi][ni][c] = 0.f;

    gemm_mainloop(A + (size_t)bm * K, BT + (size_t)bn * K, K, smem, acc);

    #pragma unroll
    for (int mi = 0; mi < 4; mi++) {
        #pragma unroll
        for (int half = 0; half < 2; half++) {
            const int row = bm + wm*64 + mi*16 + g + half*8;
            #pragma unroll
            for (int ni = 0; ni < 8; ni++) {
                const int col = bn + wn*64 + ni*8 + t4*2;
                float vx = acc[mi][ni][half*2 + 0] + __ldg(bias + col);
                float vy = acc[mi][ni][half*2 + 1] + __ldg(bias + col + 1);
                if (EPI == 1) {
                    vx += __ldg(res + (size_t)row * N + col);
                    vy += __ldg(res + (size_t)row * N + col + 1);
                } else if (EPI == 2) {
                    vx = 0.5f * vx * (1.f + erff(vx * 0.70710678118654752f));
                    vy = 0.5f * vy * (1.f + erff(vy * 0.70710678118654752f));
                    vx = tfround(vx); vy = tfround(vy);
                } else {
                    vx = tfround(vx); vy = tfround(vy);
                }
                float2 o; o.x = vx; o.y = vy;
                *reinterpret_cast<float2*>(C + (size_t)row * N + col) = o;
            }
        }
    }
}

// fused QKV: BT = wqkvT [3072][1024]; grid.x = 24 (3 outputs x 8 col-blocks)
__global__ void __launch_bounds__(128, 2) tc_gemm_qkv(
    const float* __restrict__ A, const float* __restrict__ BT,
    const float* __restrict__ bq, const float* __restrict__ bk,
    const float* __restrict__ bv,
    float* __restrict__ q, float* __restrict__ k, float* __restrict__ v, int K)
{
    extern __shared__ float smem[];
    const int t = threadIdx.x;
    const int lane = t & 31, warp = t >> 5;
    const int wm = warp >> 1, wn = warp & 1;
    const int g  = lane >> 2, t4 = lane & 3;
    const int which = blockIdx.x >> 3;
    const int bn = (blockIdx.x & 7) * 128;
    const int bm = blockIdx.y * 128;
    const float* bias = (which == 0) ? bq : (which == 1) ? bk : bv;
    float* C = (which == 0) ? q : (which == 1) ? k : v;

    float acc[4][8][4];
    #pragma unroll
    for (int mi = 0; mi < 4; mi++)
        #pragma unroll
        for (int ni = 0; ni < 8; ni++)
            #pragma unroll
            for (int c = 0; c < 4; c++) acc[mi][ni][c] = 0.f;

    gemm_mainloop(A + (size_t)bm * K, BT + (size_t)(which * Ec + bn) * K, K, smem, acc);

    #pragma unroll
    for (int mi = 0; mi < 4; mi++) {
        #pragma unroll
        for (int half = 0; half < 2; half++) {
            const int row = bm + wm*64 + mi*16 + g + half*8;
            #pragma unroll
            for (int ni = 0; ni < 8; ni++) {
                const int col = bn + wn*64 + ni*8 + t4*2;
                float vx = tfround(acc[mi][ni][half*2 + 0] + __ldg(bias + col));
                float vy = tfround(acc[mi][ni][half*2 + 1] + __ldg(bias + col + 1));
                float2 o; o.x = vx; o.y = vy;
                *reinterpret_cast<float2*>(C + (size_t)row * Ec + col) = o;
            }
        }
    }
}

// ---------------- fused flash attention (pipelined cp.async, tf32 mma) ----------
#define QS_LD 68
#define KS_LD 68
#define VS_LD 72
#define PS_LD 132
#define ATTN_SMEM ((128*QS_LD + 2*128*KS_LD + 128*VS_LD + 128*PS_LD) * 4)  // 208896

__global__ void __launch_bounds__(256) attn_kernel(
    const float* __restrict__ q, const float* __restrict__ kg,
    const float* __restrict__ vg, float* __restrict__ ctx)
{
    extern __shared__ unsigned sm[];
    unsigned* Qs = sm;
    unsigned* Ks = Qs + 128 * QS_LD;     // 2 buffers
    unsigned* Vs = Ks + 2 * 128 * KS_LD;
    unsigned* Ps = Vs + 128 * VS_LD;

    const int t = threadIdx.x, lane = t & 31, warp = t >> 5;
    const int g = lane >> 2, t4 = lane & 3;
    const int b = blockIdx.y >> 4, h = blockIdx.y & 15;
    const size_t base = (size_t)b * Sc * Ec + (size_t)h * HDc;
    const float* qp = q  + base + (size_t)blockIdx.x * 128 * Ec;
    const float* kp = kg + base;
    const float* vp = vg + base;

    const uint32_t qb = smem_u32(Qs);
    const uint32_t kb = smem_u32(Ks);
    const uint32_t vb = smem_u32(Vs);

    // prologue: Q tile + K tile 0 (group 0)
    #pragma unroll
    for (int i = 0; i < 8; i++) {
        const int lin = t + i*256;
        const int r = lin >> 4, c = (lin & 15) * 4;
        cp16(qb + (r*QS_LD + c)*4, qp + (size_t)r * Ec + c);
        cp16(kb + (r*KS_LD + c)*4, kp + (size_t)r * Ec + c);
    }
    cp_commit();

    float o[8][4];
    #pragma unroll
    for (int ni = 0; ni < 8; ni++)
        #pragma unroll
        for (int c = 0; c < 4; c++) o[ni][c] = 0.f;
    float m0 = -INFINITY, m1 = -INFINITY, l0 = 0.f, l1 = 0.f;
    const int pr0 = warp*16 + g;

    for (int kt = 0; kt < 16; kt++) {
        __syncthreads();   // prior S/PV done -> safe to overwrite Vs / other K buffer
        // V(kt) -> group
        #pragma unroll
        for (int i = 0; i < 8; i++) {
            const int lin = t + i*256;
            const int r = lin >> 4, c = (lin & 15) * 4;
            cp16(vb + (r*VS_LD + c)*4, vp + (size_t)(kt*128 + r) * Ec + c);
        }
        cp_commit();
        // K(kt+1) -> group (possibly empty)
        if (kt < 15) {
            const uint32_t kbn = kb + ((kt+1)&1) * (128*KS_LD*4);
            #pragma unroll
            for (int i = 0; i < 8; i++) {
                const int lin = t + i*256;
                const int r = lin >> 4, c = (lin & 15) * 4;
                cp16(kbn + (r*KS_LD + c)*4, kp + (size_t)((kt+1)*128 + r) * Ec + c);
            }
        }
        cp_commit();
        CP_WAIT(2);        // K(kt) (and Q) resident
        __syncthreads();

        const unsigned* Kc = Ks + (kt & 1) * 128 * KS_LD;

        // S = Q @ K^T  (per warp: 16 rows x 128 cols)
        float sacc[16][4];
        #pragma unroll
        for (int ni = 0; ni < 16; ni++)
            #pragma unroll
            for (int c = 0; c < 4; c++) sacc[ni][c] = 0.f;
        #pragma unroll
        for (int kk = 0; kk < 8; kk++) {
            const int kbo = kk * 8;
            unsigned a[4];
            a[0] = Qs[pr0      * QS_LD + kbo + t4];
            a[1] = Qs[(pr0+8)  * QS_LD + kbo + t4];
            a[2] = Qs[pr0      * QS_LD + kbo + t4 + 4];
            a[3] = Qs[(pr0+8)  * QS_LD + kbo + t4 + 4];
            #pragma unroll
            for (int ni = 0; ni < 16; ni++) {
                unsigned bb[2];
                const int j = ni*8 + g;
                bb[0] = Kc[j*KS_LD + kbo + t4];
                bb[1] = Kc[j*KS_LD + kbo + t4 + 4];
                mma8(sacc[ni], a, bb);
            }
        }

        // online softmax
        float rm0 = -INFINITY, rm1 = -INFINITY;
        #pragma unroll
        for (int ni = 0; ni < 16; ni++) {
            sacc[ni][0] *= 0.125f; sacc[ni][1] *= 0.125f;
            sacc[ni][2] *= 0.125f; sacc[ni][3] *= 0.125f;
            rm0 = fmaxf(rm0, fmaxf(sacc[ni][0], sacc[ni][1]));
            rm1 = fmaxf(rm1, fmaxf(sacc[ni][2], sacc[ni][3]));
        }
        rm0 = fmaxf(rm0, __shfl_xor_sync(0xffffffffu, rm0, 1));
        rm0 = fmaxf(rm0, __shfl_xor_sync(0xffffffffu, rm0, 2));
        rm1 = fmaxf(rm1, __shfl_xor_sync(0xffffffffu, rm1, 1));
        rm1 = fmaxf(rm1, __shfl_xor_sync(0xffffffffu, rm1, 2));
        const float mn0 = fmaxf(m0, rm0), mn1 = fmaxf(m1, rm1);
        const float al0 = __expf(m0 - mn0), al1 = __expf(m1 - mn1);
        float ps0 = 0.f, ps1 = 0.f;
        #pragma unroll
        for (int ni = 0; ni < 16; ni++) {
            float p0 = __expf(sacc[ni][0] - mn0);
            float p1 = __expf(sacc[ni][1] - mn0);
            float p2 = __expf(sacc[ni][2] - mn1);
            float p3 = __expf(sacc[ni][3] - mn1);
            ps0 += p0 + p1; ps1 += p2 + p3;
            const int col = ni*8 + t4*2;
            Ps[pr0     * PS_LD + col    ] = f2tf(p0);
            Ps[pr0     * PS_LD + col + 1] = f2tf(p1);
            Ps[(pr0+8) * PS_LD + col    ] = f2tf(p2);
            Ps[(pr0+8) * PS_LD + col + 1] = f2tf(p3);
        }
        ps0 += __shfl_xor_sync(0xffffffffu, ps0, 1);
        ps0 += __shfl_xor_sync(0xffffffffu, ps0, 2);
        ps1 += __shfl_xor_sync(0xffffffffu, ps1, 1);
        ps1 += __shfl_xor_sync(0xffffffffu, ps1, 2);
        l0 = l0 * al0 + ps0; l1 = l1 * al1 + ps1;
        m0 = mn0; m1 = mn1;
        #pragma unroll
        for (int ni = 0; ni < 8; ni++) {
            o[ni][0] *= al0; o[ni][1] *= al0;
            o[ni][2] *= al1; o[ni][3] *= al1;
        }
        __syncwarp();

        CP_WAIT(1);        // V(kt) resident (K(kt+1) may still be in flight)
        __syncthreads();

        // O += P @ V
        #pragma unroll
        for (int kk = 0; kk < 16; kk++) {
            const int kbo = kk * 8;
            unsigned a[4];
            a[0] = Ps[pr0     * PS_LD + kbo + t4];
            a[1] = Ps[(pr0+8) * PS_LD + kbo + t4];
            a[2] = Ps[pr0     * PS_LD + kbo + t4 + 4];
            a[3] = Ps[(pr0+8) * PS_LD + kbo + t4 + 4];
            #pragma unroll
            for (int ni = 0; ni < 8; ni++) {
                unsigned bb[2];
                const int d = ni*8 + g;
                bb[0] = Vs[(kbo + t4    ) * VS_LD + d];
                bb[1] = Vs[(kbo + t4 + 4) * VS_LD + d];
                mma8(o[ni], a, bb);
            }
        }
    }

    const float inv0 = 1.f / l0, inv1 = 1.f / l1;
    float* cp = ctx + base + (size_t)blockIdx.x * 128 * Ec;
    #pragma unroll
    for (int ni = 0; ni < 8; ni++) {
        const int d = ni*8 + t4*2;
        float2 u0; u0.x = tfround(o[ni][0] * inv0); u0.y = tfround(o[ni][1] * inv0);
        float2 u1; u1.x = tfround(o[ni][2] * inv1); u1.y = tfround(o[ni][3] * inv1);
        *reinterpret_cast<float2*>(cp + (size_t)pr0     * Ec + d) = u0;
        *reinterpret_cast<float2*>(cp + (size_t)(pr0+8) * Ec + d) = u1;
    }
}

// ---------------- launch ----------------
extern "C" void kernel_launch(void* const* d_in, const int* in_sizes, int n_in,
                              void* d_out, int out_size)
{
    const float* x   = (const float*)d_in[0];
    const float* wq  = (const float*)d_in[1];
    const float* bq  = (const float*)d_in[2];
    const float* wk  = (const float*)d_in[3];
    const float* bk  = (const float*)d_in[4];
    const float* wv  = (const float*)d_in[5];
    const float* bv  = (const float*)d_in[6];
    const float* wo  = (const float*)d_in[7];
    const float* bo  = (const float*)d_in[8];
    const float* w1  = (const float*)d_in[9];
    const float* b1  = (const float*)d_in[10];
    const float* w2  = (const float*)d_in[11];
    const float* b2  = (const float*)d_in[12];
    const float* g1  = (const float*)d_in[13];
    const float* be1 = (const float*)d_in[14];
    const float* g2  = (const float*)d_in[15];
    const float* be2 = (const float*)d_in[16];
    float* out = (float*)d_out;

    float *z0, *q, *k, *v, *ctx, *x1, *z1, *h;
    float *wqkvT, *woT, *w1T, *w2T;
    cudaGetSymbolAddress((void**)&z0,   g_z0);
    cudaGetSymbolAddress((void**)&q,    g_q);
    cudaGetSymbolAddress((void**)&k,    g_k);
    cudaGetSymbolAddress((void**)&v,    g_v);
    cudaGetSymbolAddress((void**)&ctx,  g_ctx);
    cudaGetSymbolAddress((void**)&x1,   g_x1);
    cudaGetSymbolAddress((void**)&z1,   g_z1);
    cudaGetSymbolAddress((void**)&h,    g_h);
    cudaGetSymbolAddress((void**)&wqkvT, g_wqkvT);
    cudaGetSymbolAddress((void**)&woT,  g_woT);
    cudaGetSymbolAddress((void**)&w1T,  g_w1T);
    cudaGetSymbolAddress((void**)&w2T,  g_w2T);

    cudaFuncSetAttribute(attn_kernel,  cudaFuncAttributeMaxDynamicSharedMemorySize, ATTN_SMEM);
    cudaFuncSetAttribute(tc_gemm<0>,   cudaFuncAttributeMaxDynamicSharedMemorySize, SMEM_GEMM);
    cudaFuncSetAttribute(tc_gemm<1>,   cudaFuncAttributeMaxDynamicSharedMemorySize, SMEM_GEMM);
    cudaFuncSetAttribute(tc_gemm<2>,   cudaFuncAttributeMaxDynamicSharedMemorySize, SMEM_GEMM);
    cudaFuncSetAttribute(tc_gemm_qkv,  cudaFuncAttributeMaxDynamicSharedMemorySize, SMEM_GEMM);

    // 1
    ln_kernel<<<TOK, 256>>>(x, g1, be1, z0);
    // 2: wq,wk,wv -> wqkvT slices; wo -> woT
    transpose4_kernel<<<dim3(32, 32, 4), 256>>>(
        wq, wk, wv, wo,
        wqkvT, wqkvT + (size_t)Ec*Ec, wqkvT + (size_t)2*Ec*Ec, woT);
    // 3
    transpose_kernel<<<dim3(MLPc/32, Ec/32), 256>>>(w1, w1T, Ec, MLPc);
    // 4
    tc_gemm_qkv<<<dim3(24, TOK/128), 128, SMEM_GEMM>>>(z0, wqkvT, bq, bk, bv, q, k, v, Ec);
    // 5
    attn_kernel<<<dim3(Sc/128, Bc*Hc), 256, ATTN_SMEM>>>(q, k, v, ctx);
    // 6  <- profiled by ncu (-s 5 -c 1)
    tc_gemm<1><<<dim3(Ec/128, TOK/128), 128, SMEM_GEMM>>>(ctx, woT, bo, x, x1, TOK, Ec, Ec);
    // 7
    ln_kernel<<<TOK, 256>>>(x1, g2, be2, z1);
    // 8
    transpose_kernel<<<dim3(Ec/32, MLPc/32), 256>>>(w2, w2T, MLPc, Ec);
    // 9
    tc_gemm<2><<<dim3(MLPc/128, TOK/128), 128, SMEM_GEMM>>>(z1, w1T, b1, nullptr, h, TOK, MLPc, Ec);
    // 10
    tc_gemm<1><<<dim3(Ec/128, TOK/128), 128, SMEM_GEMM>>>(h, w2T, b2, x1, out, TOK, Ec, MLPc);
}

// round 5
// speedup vs baseline: 1.4395x; 1.0642x over previous
#include <cuda_runtime.h>
#include <cstdint>
#include <math.h>

#define Bc   2
#define Sc   2048
#define TOK  4096
#define Ec   1024
#define Hc   16
#define HDc  64
#define MLPc 4096

// ---------------- scratch (no allocations allowed) ----------------
__device__ float g_z0[(size_t)TOK * Ec];
__device__ float g_q [(size_t)TOK * Ec];
__device__ float g_k [(size_t)TOK * Ec];
__device__ float g_v [(size_t)TOK * Ec];
__device__ float g_ctx[(size_t)TOK * Ec];
__device__ float g_x1[(size_t)TOK * Ec];
__device__ float g_z1[(size_t)TOK * Ec];
__device__ float g_h [(size_t)TOK * MLPc];
__device__ float g_wqkvT[(size_t)3 * Ec * Ec];
__device__ float g_woT[(size_t)Ec * Ec];
__device__ float g_w1T[(size_t)Ec * MLPc];
__device__ float g_w2T[(size_t)MLPc * Ec];

// ---------------- helpers ----------------
__device__ __forceinline__ unsigned f2tf(float f) {
    unsigned r;
    asm("cvt.rna.tf32.f32 %0, %1;" : "=r"(r) : "f"(f));
    return r;
}
__device__ __forceinline__ float tfround(float f) {
    return __uint_as_float(f2tf(f));
}
__device__ __forceinline__ uint32_t smem_u32(const void* p) {
    uint32_t a;
    asm("{ .reg .u64 t; cvta.to.shared.u64 t, %1; cvt.u32.u64 %0, t; }" : "=r"(a) : "l"(p));
    return a;
}
__device__ __forceinline__ void cp16(uint32_t d, const void* s) {
    asm volatile("cp.async.cg.shared.global [%0], [%1], 16;\n" :: "r"(d), "l"(s));
}
__device__ __forceinline__ void cp_commit() {
    asm volatile("cp.async.commit_group;\n" ::: "memory");
}
#define CP_WAIT(n) asm volatile("cp.async.wait_group %0;\n" :: "n"(n) : "memory")

__device__ __forceinline__ void mma8(float c[4], const unsigned a[4], const unsigned b[2]) {
    asm volatile(
        "mma.sync.aligned.m16n8k8.row.col.f32.tf32.tf32.f32 "
        "{%0,%1,%2,%3}, {%4,%5,%6,%7}, {%8,%9}, {%0,%1,%2,%3};\n"
        : "+f"(c[0]), "+f"(c[1]), "+f"(c[2]), "+f"(c[3])
        : "r"(a[0]), "r"(a[1]), "r"(a[2]), "r"(a[3]),
          "r"(b[0]), "r"(b[1]));
}

// ---------------- weight transposes (+ tf32 rounding) ----------------
__global__ void __launch_bounds__(256) transpose4_kernel(
    const float* __restrict__ i0, const float* __restrict__ i1,
    const float* __restrict__ i2, const float* __restrict__ i3,
    float* __restrict__ o0, float* __restrict__ o1,
    float* __restrict__ o2, float* __restrict__ o3)
{
    const float* in  = (blockIdx.z == 0) ? i0 : (blockIdx.z == 1) ? i1 : (blockIdx.z == 2) ? i2 : i3;
    float*       out = (blockIdx.z == 0) ? o0 : (blockIdx.z == 1) ? o1 : (blockIdx.z == 2) ? o2 : o3;
    __shared__ float tile[32][33];
    const int bx = blockIdx.x * 32, by = blockIdx.y * 32;
    const int tx = threadIdx.x & 31, ty = threadIdx.x >> 5;
    #pragma unroll
    for (int i = 0; i < 32; i += 8)
        tile[ty + i][tx] = tfround(in[(size_t)(by + ty + i) * Ec + bx + tx]);
    __syncthreads();
    #pragma unroll
    for (int i = 0; i < 32; i += 8)
        out[(size_t)(bx + ty + i) * Ec + by + tx] = tile[tx][ty + i];
}

__global__ void __launch_bounds__(256) transpose_kernel(
    const float* __restrict__ in, float* __restrict__ out, int R, int C)
{
    __shared__ float tile[32][33];
    const int bx = blockIdx.x * 32, by = blockIdx.y * 32;
    const int tx = threadIdx.x & 31, ty = threadIdx.x >> 5;
    #pragma unroll
    for (int i = 0; i < 32; i += 8)
        tile[ty + i][tx] = tfround(in[(size_t)(by + ty + i) * C + bx + tx]);
    __syncthreads();
    #pragma unroll
    for (int i = 0; i < 32; i += 8)
        out[(size_t)(bx + ty + i) * R + by + tx] = tile[tx][ty + i];
}

// ---------------- LayerNorm (fp32 exact, tf32-rounded output) ----------------
__global__ void __launch_bounds__(256) ln_kernel(
    const float* __restrict__ x, const float* __restrict__ gam,
    const float* __restrict__ bet, float* __restrict__ y)
{
    const int row = blockIdx.x, t = threadIdx.x;
    const float4* xr = reinterpret_cast<const float4*>(x + (size_t)row * Ec);
    float4 v = xr[t];
    float s  = v.x + v.y + v.z + v.w;
    float ss = v.x*v.x + v.y*v.y + v.z*v.z + v.w*v.w;
    #pragma unroll
    for (int o = 16; o; o >>= 1) {
        s  += __shfl_xor_sync(0xffffffffu, s,  o);
        ss += __shfl_xor_sync(0xffffffffu, ss, o);
    }
    __shared__ float rs[8], rss[8];
    if ((t & 31) == 0) { rs[t >> 5] = s; rss[t >> 5] = ss; }
    __syncthreads();
    if (t < 32) {
        float a = (t < 8) ? rs[t]  : 0.f;
        float b = (t < 8) ? rss[t] : 0.f;
        #pragma unroll
        for (int o = 4; o; o >>= 1) {
            a += __shfl_xor_sync(0xffffffffu, a, o);
            b += __shfl_xor_sync(0xffffffffu, b, o);
        }
        if (t == 0) { rs[0] = a; rss[0] = b; }
    }
    __syncthreads();
    const float mu   = rs[0]  * (1.f / Ec);
    const float var  = rss[0] * (1.f / Ec) - mu * mu;
    const float rstd = rsqrtf(var + 1e-5f);
    float4 gv = reinterpret_cast<const float4*>(gam)[t];
    float4 bv = reinterpret_cast<const float4*>(bet)[t];
    float4 o;
    o.x = tfround((v.x - mu) * rstd * gv.x + bv.x);
    o.y = tfround((v.y - mu) * rstd * gv.y + bv.y);
    o.z = tfround((v.z - mu) * rstd * gv.z + bv.z);
    o.w = tfround((v.w - mu) * rstd * gv.w + bv.w);
    reinterpret_cast<float4*>(y + (size_t)row * Ec)[t] = o;
}

// ---------------- TF32 GEMM mainloop (3-stage, k-tile 32, frag double-buffer) ---
#define KT   32
#define SW   36                    // words per 32-float row (+4 pad)
#define STG  (128 * SW)            // words per operand stage (4608)
#define NSTG 3
#define SMEM_GEMM (2 * NSTG * STG * 4)   // 110592 bytes

__device__ __forceinline__ void ldstage(uint32_t ab, uint32_t bb,
    const float* __restrict__ Ap, const float* __restrict__ Bp, int K, int kt)
{
    const int t = threadIdx.x;
    const int k0 = kt * KT;
    #pragma unroll
    for (int i = 0; i < 8; i++) {
        const int idx = t + i * 128;
        const int r = idx >> 3, cu = (idx & 7) * 4;
        cp16(ab + (r * SW + cu) * 4, Ap + (size_t)r * K + k0 + cu);
    }
    #pragma unroll
    for (int i = 0; i < 8; i++) {
        const int idx = t + i * 128;
        const int r = idx >> 3, cu = (idx & 7) * 4;
        cp16(bb + (r * SW + cu) * 4, Bp + (size_t)r * K + k0 + cu);
    }
}

__device__ __forceinline__ void ldfrag(
    unsigned af[4][4], unsigned bf[8][2],
    const float* __restrict__ as, const float* __restrict__ bs,
    int kb, int wm, int wn, int g, int t4)
{
    #pragma unroll
    for (int mi = 0; mi < 4; mi++) {
        const float* ar = as + (wm*64 + mi*16 + g) * SW + kb + t4;
        af[mi][0] = __float_as_uint(ar[0]);
        af[mi][1] = __float_as_uint(ar[8 * SW]);
        af[mi][2] = __float_as_uint(ar[4]);
        af[mi][3] = __float_as_uint(ar[8 * SW + 4]);
    }
    #pragma unroll
    for (int ni = 0; ni < 8; ni++) {
        const float* br = bs + (wn*64 + ni*8 + g) * SW + kb + t4;
        bf[ni][0] = __float_as_uint(br[0]);
        bf[ni][1] = __float_as_uint(br[4]);
    }
}

__device__ __forceinline__ void gemm_mainloop(
    const float* __restrict__ Ap, const float* __restrict__ Bp, int K,
    float* smem, float acc[4][8][4])
{
    const int t    = threadIdx.x;
    const int lane = t & 31, warp = t >> 5;
    const int wm = warp >> 1, wn = warp & 1;
    const int g  = lane >> 2, t4 = lane & 3;
    const int NK = K / KT;

    const uint32_t asb = smem_u32(smem);
    const uint32_t bsb = asb + NSTG * STG * 4;

    // prologue: stages 0,1
    ldstage(asb, bsb, Ap, Bp, K, 0);
    cp_commit();
    ldstage(asb + STG*4, bsb + STG*4, Ap, Bp, K, 1);
    cp_commit();

    unsigned af[2][4][4], bf[2][8][2];
    int st = 0;
    for (int kt = 0; kt < NK; kt++) {
        CP_WAIT(1);
        __syncthreads();
        const float* as = smem + st * STG;
        const float* bs = smem + NSTG * STG + st * STG;
        ldfrag(af[0], bf[0], as, bs, 0, wm, wn, g, t4);
        // prefetch stage kt+2
        if (kt + 2 < NK) {
            int ps = st + 2; if (ps >= NSTG) ps -= NSTG;
            ldstage(asb + ps * STG * 4, bsb + ps * STG * 4, Ap, Bp, K, kt + 2);
        }
        cp_commit();
        #pragma unroll
        for (int kb = 0; kb < 4; kb++) {
            const int cur = kb & 1;
            if (kb < 3)
                ldfrag(af[cur ^ 1], bf[cur ^ 1], as, bs, (kb + 1) * 8, wm, wn, g, t4);
            #pragma unroll
            for (int mi = 0; mi < 4; mi++)
                #pragma unroll
                for (int ni = 0; ni < 8; ni++)
                    mma8(acc[mi][ni], af[cur][mi], bf[cur][ni]);
        }
        st++; if (st == NSTG) st = 0;
    }
}

// EPI: 0 = bias(->tf32), 1 = bias+res (fp32), 2 = bias+gelu(->tf32)
template <int EPI>
__global__ void __launch_bounds__(128, 2) tc_gemm(
    const float* __restrict__ A, const float* __restrict__ BT,
    const float* __restrict__ bias, const float* __restrict__ res,
    float* __restrict__ C, int M, int N, int K)
{
    extern __shared__ float smem[];
    const int t = threadIdx.x;
    const int lane = t & 31, warp = t >> 5;
    const int wm = warp >> 1, wn = warp & 1;
    const int g  = lane >> 2, t4 = lane & 3;
    const int bm = blockIdx.y * 128, bn = blockIdx.x * 128;

    float acc[4][8][4];
    #pragma unroll
    for (int mi = 0; mi < 4; mi++)
        #pragma unroll
        for (int ni = 0; ni < 8; ni++)
            #pragma unroll
            for (int c = 0; c < 4; c++) acc[mi][ni][c] = 0.f;

    gemm_mainloop(A + (size_t)bm * K, BT + (size_t)bn * K, K, smem, acc);

    #pragma unroll
    for (int mi = 0; mi < 4; mi++) {
        #pragma unroll
        for (int half = 0; half < 2; half++) {
            const int row = bm + wm*64 + mi*16 + g + half*8;
            #pragma unroll
            for (int ni = 0; ni < 8; ni++) {
                const int col = bn + wn*64 + ni*8 + t4*2;
                float vx = acc[mi][ni][half*2 + 0] + __ldg(bias + col);
                float vy = acc[mi][ni][half*2 + 1] + __ldg(bias + col + 1);
                if (EPI == 1) {
                    vx += __ldg(res + (size_t)row * N + col);
                    vy += __ldg(res + (size_t)row * N + col + 1);
                } else if (EPI == 2) {
                    vx = 0.5f * vx * (1.f + erff(vx * 0.70710678118654752f));
                    vy = 0.5f * vy * (1.f + erff(vy * 0.70710678118654752f));
                    vx = tfround(vx); vy = tfround(vy);
                } else {
                    vx = tfround(vx); vy = tfround(vy);
                }
                float2 o; o.x = vx; o.y = vy;
                *reinterpret_cast<float2*>(C + (size_t)row * N + col) = o;
            }
        }
    }
}

// fused QKV: BT = wqkvT [3072][1024]; grid.x = 24 (3 outputs x 8 col-blocks)
__global__ void __launch_bounds__(128, 2) tc_gemm_qkv(
    const float* __restrict__ A, const float* __restrict__ BT,
    const float* __restrict__ bq, const float* __restrict__ bk,
    const float* __restrict__ bv,
    float* __restrict__ q, float* __restrict__ k, float* __restrict__ v, int K)
{
    extern __shared__ float smem[];
    const int t = threadIdx.x;
    const int lane = t & 31, warp = t >> 5;
    const int wm = warp >> 1, wn = warp & 1;
    const int g  = lane >> 2, t4 = lane & 3;
    const int which = blockIdx.x >> 3;
    const int bn = (blockIdx.x & 7) * 128;
    const int bm = blockIdx.y * 128;
    const float* bias = (which == 0) ? bq : (which == 1) ? bk : bv;
    float* C = (which == 0) ? q : (which == 1) ? k : v;

    float acc[4][8][4];
    #pragma unroll
    for (int mi = 0; mi < 4; mi++)
        #pragma unroll
        for (int ni = 0; ni < 8; ni++)
            #pragma unroll
            for (int c = 0; c < 4; c++) acc[mi][ni][c] = 0.f;

    gemm_mainloop(A + (size_t)bm * K, BT + (size_t)(which * Ec + bn) * K, K, smem, acc);

    #pragma unroll
    for (int mi = 0; mi < 4; mi++) {
        #pragma unroll
        for (int half = 0; half < 2; half++) {
            const int row = bm + wm*64 + mi*16 + g + half*8;
            #pragma unroll
            for (int ni = 0; ni < 8; ni++) {
                const int col = bn + wn*64 + ni*8 + t4*2;
                float vx = tfround(acc[mi][ni][half*2 + 0] + __ldg(bias + col));
                float vy = tfround(acc[mi][ni][half*2 + 1] + __ldg(bias + col + 1));
                float2 o; o.x = vx; o.y = vy;
                *reinterpret_cast<float2*>(C + (size_t)row * Ec + col) = o;
            }
        }
    }
}

// ---------------- fused flash attention (pipelined cp.async, tf32 mma) ----------
#define QS_LD 68
#define KS_LD 68
#define VS_LD 72
#define PS_LD 132
#define ATTN_SMEM ((128*QS_LD + 2*128*KS_LD + 128*VS_LD + 128*PS_LD) * 4)  // 208896

__global__ void __launch_bounds__(256) attn_kernel(
    const float* __restrict__ q, const float* __restrict__ kg,
    const float* __restrict__ vg, float* __restrict__ ctx)
{
    extern __shared__ unsigned sm[];
    unsigned* Qs = sm;
    unsigned* Ks = Qs + 128 * QS_LD;     // 2 buffers
    unsigned* Vs = Ks + 2 * 128 * KS_LD;
    unsigned* Ps = Vs + 128 * VS_LD;

    const int t = threadIdx.x, lane = t & 31, warp = t >> 5;
    const int g = lane >> 2, t4 = lane & 3;
    const int b = blockIdx.y >> 4, h = blockIdx.y & 15;
    const size_t base = (size_t)b * Sc * Ec + (size_t)h * HDc;
    const float* qp = q  + base + (size_t)blockIdx.x * 128 * Ec;
    const float* kp = kg + base;
    const float* vp = vg + base;

    const uint32_t qb = smem_u32(Qs);
    const uint32_t kb = smem_u32(Ks);
    const uint32_t vb = smem_u32(Vs);

    // prologue: Q tile + K tile 0 (group 0)
    #pragma unroll
    for (int i = 0; i < 8; i++) {
        const int lin = t + i*256;
        const int r = lin >> 4, c = (lin & 15) * 4;
        cp16(qb + (r*QS_LD + c)*4, qp + (size_t)r * Ec + c);
        cp16(kb + (r*KS_LD + c)*4, kp + (size_t)r * Ec + c);
    }
    cp_commit();

    float o[8][4];
    #pragma unroll
    for (int ni = 0; ni < 8; ni++)
        #pragma unroll
        for (int c = 0; c < 4; c++) o[ni][c] = 0.f;
    float m0 = -INFINITY, m1 = -INFINITY, l0 = 0.f, l1 = 0.f;
    const int pr0 = warp*16 + g;

    for (int kt = 0; kt < 16; kt++) {
        __syncthreads();
        #pragma unroll
        for (int i = 0; i < 8; i++) {
            const int lin = t + i*256;
            const int r = lin >> 4, c = (lin & 15) * 4;
            cp16(vb + (r*VS_LD + c)*4, vp + (size_t)(kt*128 + r) * Ec + c);
        }
        cp_commit();
        if (kt < 15) {
            const uint32_t kbn = kb + ((kt+1)&1) * (128*KS_LD*4);
            #pragma unroll
            for (int i = 0; i < 8; i++) {
                const int lin = t + i*256;
                const int r = lin >> 4, c = (lin & 15) * 4;
                cp16(kbn + (r*KS_LD + c)*4, kp + (size_t)((kt+1)*128 + r) * Ec + c);
            }
        }
        cp_commit();
        CP_WAIT(2);
        __syncthreads();

        const unsigned* Kc = Ks + (kt & 1) * 128 * KS_LD;

        float sacc[16][4];
        #pragma unroll
        for (int ni = 0; ni < 16; ni++)
            #pragma unroll
            for (int c = 0; c < 4; c++) sacc[ni][c] = 0.f;
        #pragma unroll
        for (int kk = 0; kk < 8; kk++) {
            const int kbo = kk * 8;
            unsigned a[4];
            a[0] = Qs[pr0      * QS_LD + kbo + t4];
            a[1] = Qs[(pr0+8)  * QS_LD + kbo + t4];
            a[2] = Qs[pr0      * QS_LD + kbo + t4 + 4];
            a[3] = Qs[(pr0+8)  * QS_LD + kbo + t4 + 4];
            #pragma unroll
            for (int ni = 0; ni < 16; ni++) {
                unsigned bb[2];
                const int j = ni*8 + g;
                bb[0] = Kc[j*KS_LD + kbo + t4];
                bb[1] = Kc[j*KS_LD + kbo + t4 + 4];
                mma8(sacc[ni], a, bb);
            }
        }

        float rm0 = -INFINITY, rm1 = -INFINITY;
        #pragma unroll
        for (int ni = 0; ni < 16; ni++) {
            sacc[ni][0] *= 0.125f; sacc[ni][1] *= 0.125f;
            sacc[ni][2] *= 0.125f; sacc[ni][3] *= 0.125f;
            rm0 = fmaxf(rm0, fmaxf(sacc[ni][0], sacc[ni][1]));
            rm1 = fmaxf(rm1, fmaxf(sacc[ni][2], sacc[ni][3]));
        }
        rm0 = fmaxf(rm0, __shfl_xor_sync(0xffffffffu, rm0, 1));
        rm0 = fmaxf(rm0, __shfl_xor_sync(0xffffffffu, rm0, 2));
        rm1 = fmaxf(rm1, __shfl_xor_sync(0xffffffffu, rm1, 1));
        rm1 = fmaxf(rm1, __shfl_xor_sync(0xffffffffu, rm1, 2));
        const float mn0 = fmaxf(m0, rm0), mn1 = fmaxf(m1, rm1);
        const float al0 = __expf(m0 - mn0), al1 = __expf(m1 - mn1);
        float ps0 = 0.f, ps1 = 0.f;
        #pragma unroll
        for (int ni = 0; ni < 16; ni++) {
            float p0 = __expf(sacc[ni][0] - mn0);
            float p1 = __expf(sacc[ni][1] - mn0);
            float p2 = __expf(sacc[ni][2] - mn1);
            float p3 = __expf(sacc[ni][3] - mn1);
            ps0 += p0 + p1; ps1 += p2 + p3;
            const int col = ni*8 + t4*2;
            Ps[pr0     * PS_LD + col    ] = __float_as_uint(p0);
            Ps[pr0     * PS_LD + col + 1] = __float_as_uint(p1);
            Ps[(pr0+8) * PS_LD + col    ] = __float_as_uint(p2);
            Ps[(pr0+8) * PS_LD + col + 1] = __float_as_uint(p3);
        }
        ps0 += __shfl_xor_sync(0xffffffffu, ps0, 1);
        ps0 += __shfl_xor_sync(0xffffffffu, ps0, 2);
        ps1 += __shfl_xor_sync(0xffffffffu, ps1, 1);
        ps1 += __shfl_xor_sync(0xffffffffu, ps1, 2);
        l0 = l0 * al0 + ps0; l1 = l1 * al1 + ps1;
        m0 = mn0; m1 = mn1;
        #pragma unroll
        for (int ni = 0; ni < 8; ni++) {
            o[ni][0] *= al0; o[ni][1] *= al0;
            o[ni][2] *= al1; o[ni][3] *= al1;
        }
        __syncwarp();

        CP_WAIT(1);
        __syncthreads();

        #pragma unroll
        for (int kk = 0; kk < 16; kk++) {
            const int kbo = kk * 8;
            unsigned a[4];
            a[0] = Ps[pr0     * PS_LD + kbo + t4];
            a[1] = Ps[(pr0+8) * PS_LD + kbo + t4];
            a[2] = Ps[pr0     * PS_LD + kbo + t4 + 4];
            a[3] = Ps[(pr0+8) * PS_LD + kbo + t4 + 4];
            #pragma unroll
            for (int ni = 0; ni < 8; ni++) {
                unsigned bb[2];
                const int d = ni*8 + g;
                bb[0] = Vs[(kbo + t4    ) * VS_LD + d];
                bb[1] = Vs[(kbo + t4 + 4) * VS_LD + d];
                mma8(o[ni], a, bb);
            }
        }
    }

    const float inv0 = 1.f / l0, inv1 = 1.f / l1;
    float* cp = ctx + base + (size_t)blockIdx.x * 128 * Ec;
    #pragma unroll
    for (int ni = 0; ni < 8; ni++) {
        const int d = ni*8 + t4*2;
        float2 u0; u0.x = tfround(o[ni][0] * inv0); u0.y = tfround(o[ni][1] * inv0);
        float2 u1; u1.x = tfround(o[ni][2] * inv1); u1.y = tfround(o[ni][3] * inv1);
        *reinterpret_cast<float2*>(cp + (size_t)pr0     * Ec + d) = u0;
        *reinterpret_cast<float2*>(cp + (size_t)(pr0+8) * Ec + d) = u1;
    }
}

// ---------------- launch ----------------
extern "C" void kernel_launch(void* const* d_in, const int* in_sizes, int n_in,
                              void* d_out, int out_size)
{
    const float* x   = (const float*)d_in[0];
    const float* wq  = (const float*)d_in[1];
    const float* bq  = (const float*)d_in[2];
    const float* wk  = (const float*)d_in[3];
    const float* bk  = (const float*)d_in[4];
    const float* wv  = (const float*)d_in[5];
    const float* bv  = (const float*)d_in[6];
    const float* wo  = (const float*)d_in[7];
    const float* bo  = (const float*)d_in[8];
    const float* w1  = (const float*)d_in[9];
    const float* b1  = (const float*)d_in[10];
    const float* w2  = (const float*)d_in[11];
    const float* b2  = (const float*)d_in[12];
    const float* g1  = (const float*)d_in[13];
    const float* be1 = (const float*)d_in[14];
    const float* g2  = (const float*)d_in[15];
    const float* be2 = (const float*)d_in[16];
    float* out = (float*)d_out;

    float *z0, *q, *k, *v, *ctx, *x1, *z1, *h;
    float *wqkvT, *woT, *w1T, *w2T;
    cudaGetSymbolAddress((void**)&z0,   g_z0);
    cudaGetSymbolAddress((void**)&q,    g_q);
    cudaGetSymbolAddress((void**)&k,    g_k);
    cudaGetSymbolAddress((void**)&v,    g_v);
    cudaGetSymbolAddress((void**)&ctx,  g_ctx);
    cudaGetSymbolAddress((void**)&x1,   g_x1);
    cudaGetSymbolAddress((void**)&z1,   g_z1);
    cudaGetSymbolAddress((void**)&h,    g_h);
    cudaGetSymbolAddress((void**)&wqkvT, g_wqkvT);
    cudaGetSymbolAddress((void**)&woT,  g_woT);
    cudaGetSymbolAddress((void**)&w1T,  g_w1T);
    cudaGetSymbolAddress((void**)&w2T,  g_w2T);

    cudaFuncSetAttribute(attn_kernel,  cudaFuncAttributeMaxDynamicSharedMemorySize, ATTN_SMEM);
    cudaFuncSetAttribute(tc_gemm<0>,   cudaFuncAttributeMaxDynamicSharedMemorySize, SMEM_GEMM);
    cudaFuncSetAttribute(tc_gemm<1>,   cudaFuncAttributeMaxDynamicSharedMemorySize, SMEM_GEMM);
    cudaFuncSetAttribute(tc_gemm<2>,   cudaFuncAttributeMaxDynamicSharedMemorySize, SMEM_GEMM);
    cudaFuncSetAttribute(tc_gemm_qkv,  cudaFuncAttributeMaxDynamicSharedMemorySize, SMEM_GEMM);

    // 1
    ln_kernel<<<TOK, 256>>>(x, g1, be1, z0);
    // 2
    transpose4_kernel<<<dim3(32, 32, 4), 256>>>(
        wq, wk, wv, wo,
        wqkvT, wqkvT + (size_t)Ec*Ec, wqkvT + (size_t)2*Ec*Ec, woT);
    // 3
    transpose_kernel<<<dim3(MLPc/32, Ec/32), 256>>>(w1, w1T, Ec, MLPc);
    // 4
    tc_gemm_qkv<<<dim3(24, TOK/128), 128, SMEM_GEMM>>>(z0, wqkvT, bq, bk, bv, q, k, v, Ec);
    // 5
    attn_kernel<<<dim3(Sc/128, Bc*Hc), 256, ATTN_SMEM>>>(q, k, v, ctx);
    // 6  <- profiled by ncu (-s 5 -c 1)
    tc_gemm<1><<<dim3(Ec/128, TOK/128), 128, SMEM_GEMM>>>(ctx, woT, bo, x, x1, TOK, Ec, Ec);
    // 7
    ln_kernel<<<TOK, 256>>>(x1, g2, be2, z1);
    // 8
    transpose_kernel<<<dim3(Ec/32, MLPc/32), 256>>>(w2, w2T, MLPc, Ec);
    // 9
    tc_gemm<2><<<dim3(MLPc/128, TOK/128), 128, SMEM_GEMM>>>(z1, w1T, b1, nullptr, h, TOK, MLPc, Ec);
    // 10
    tc_gemm<1><<<dim3(Ec/128, TOK/128), 128, SMEM_GEMM>>>(h, w2T, b2, x1, out, TOK, Ec, MLPc);
}